// round 3
// baseline (speedup 1.0000x reference)
#include <cuda_runtime.h>
#include <cuda_bf16.h>
#include <mma.h>

using namespace nvcuda;

// Problem constants
constexpr int Bc  = 2;
constexpr int Lc  = 2048;
constexpr int Dc  = 2048;
constexpr int Hc  = 16;
constexpr int DHc = 128;

constexpr int BDIM = 256;
__device__ __constant__ float SCALE_C = 0.08838834764831845f; // 1/sqrt(128)

// Scratch (static device globals: allocation-free per harness rules)
__device__ float g_Q[(size_t)Bc * Hc * Lc * DHc];
__device__ float g_K[(size_t)Bc * Hc * Lc * DHc];
__device__ float g_V[(size_t)Bc * Hc * Lc * DHc];
__device__ float g_A[(size_t)Bc * Lc * Dc];

// ---------------------------------------------------------------------------
// cp.async helpers
// ---------------------------------------------------------------------------
__device__ __forceinline__ void cp_async16(float* smem_dst, const float* gmem_src) {
    unsigned s = (unsigned)__cvta_generic_to_shared(smem_dst);
    asm volatile("cp.async.cg.shared.global [%0], [%1], 16;\n" :: "r"(s), "l"(gmem_src));
}
__device__ __forceinline__ void cp_commit() {
    asm volatile("cp.async.commit_group;\n");
}
template <int N>
__device__ __forceinline__ void cp_wait() {
    asm volatile("cp.async.wait_group %0;\n" :: "n"(N));
}

// ---------------------------------------------------------------------------
// TF32 WMMA GEMM core, 3-stage cp.async pipeline.
// Computes a 128x128 tile of C = X * W^T   (K = Dc, both operands row-major)
// Result left in smem as cs[128][132] (fp32) with trailing __syncthreads().
// blockDim = 256. smem: 6 buffers of [128][36] floats = 110592 B; the result
// tile cs[128][132] reuses the same region.
// ---------------------------------------------------------------------------
constexpr int XBUF = 128 * 36;   // 4608 floats per stage buffer
constexpr int NSTG = 3;

__device__ __forceinline__ void ld_chunk_async(const float* __restrict__ X,
                                               const float* __restrict__ W,
                                               float* xs, float* ws,
                                               int m0, int n0, int k0, int tid) {
#pragma unroll
    for (int i = 0; i < 4; i++) {
        int fi = tid + BDIM * i;          // 1024 float4 per matrix
        int r  = fi >> 3;                 // 8 float4 per 32-float row
        int c  = (fi & 7) << 2;
        cp_async16(xs + r * 36 + c, X + (size_t)(m0 + r) * Dc + k0 + c);
        cp_async16(ws + r * 36 + c, W + (size_t)(n0 + r) * Dc + k0 + c);
    }
}

__device__ __forceinline__ void gemm_core(const float* __restrict__ X,
                                          const float* __restrict__ W,
                                          float* sm) {
    const int tid = threadIdx.x;
    const int m0 = blockIdx.y * 128;
    const int n0 = blockIdx.x * 128;
    float* xb = sm;                       // NSTG x [128][36]
    float* wb = sm + NSTG * XBUF;         // NSTG x [128][36]
    const int warp = tid >> 5;
    const int wm = warp & 3;              // 4 warps along M (32 rows)
    const int wn = warp >> 2;             // 2 warps along N (64 cols)

    wmma::fragment<wmma::accumulator, 16, 16, 8, float> cf[2][4];
#pragma unroll
    for (int i = 0; i < 2; i++)
#pragma unroll
        for (int j = 0; j < 4; j++)
            wmma::fill_fragment(cf[i][j], 0.0f);

    constexpr int NC = Dc / 32;           // 64 K-chunks
    // Prologue: prefetch chunks 0 and 1 (one commit-group each)
    ld_chunk_async(X, W, xb, wb, m0, n0, 0, tid);
    cp_commit();
    ld_chunk_async(X, W, xb + XBUF, wb + XBUF, m0, n0, 32, tid);
    cp_commit();

    int buf = 0;
    for (int c = 0; c < NC; c++) {
        // Prefetch chunk c+2 into the buffer consumed at iter c-1.
        // (Trailing __syncthreads of iter c-1 guarantees it is free.)
        if (c + 2 < NC) {
            int nb = buf + 2; if (nb >= NSTG) nb -= NSTG;
            ld_chunk_async(X, W, xb + nb * XBUF, wb + nb * XBUF,
                           m0, n0, (c + 2) * 32, tid);
        }
        cp_commit();                      // always commit (possibly empty group)
        cp_wait<2>();                     // chunk c resident
        __syncthreads();

        float* xs = xb + buf * XBUF;
        float* ws = wb + buf * XBUF;
#pragma unroll
        for (int kk = 0; kk < 32; kk += 8) {
            wmma::fragment<wmma::matrix_a, 16, 16, 8, wmma::precision::tf32, wmma::row_major> af[2];
            wmma::fragment<wmma::matrix_b, 16, 16, 8, wmma::precision::tf32, wmma::col_major> bf[4];
#pragma unroll
            for (int i = 0; i < 2; i++) {
                wmma::load_matrix_sync(af[i], xs + (wm * 32 + i * 16) * 36 + kk, 36);
#pragma unroll
                for (int t = 0; t < af[i].num_elements; t++)
                    af[i].x[t] = wmma::__float_to_tf32(af[i].x[t]);
            }
#pragma unroll
            for (int j = 0; j < 4; j++) {
                wmma::load_matrix_sync(bf[j], ws + (wn * 64 + j * 16) * 36 + kk, 36);
#pragma unroll
                for (int t = 0; t < bf[j].num_elements; t++)
                    bf[j].x[t] = wmma::__float_to_tf32(bf[j].x[t]);
            }
#pragma unroll
            for (int i = 0; i < 2; i++)
#pragma unroll
                for (int j = 0; j < 4; j++)
                    wmma::mma_sync(cf[i][j], af[i], bf[j], cf[i][j]);
        }
        __syncthreads();                  // buffer `buf` free for prefetch at c+1
        buf++; if (buf == NSTG) buf = 0;
    }

    float* cs = sm;                       // [128][132], reuses pipeline buffers
#pragma unroll
    for (int i = 0; i < 2; i++)
#pragma unroll
        for (int j = 0; j < 4; j++)
            wmma::store_matrix_sync(cs + (wm * 32 + i * 16) * 132 + wn * 64 + j * 16,
                                    cf[i][j], 132, wmma::mem_row_major);
    __syncthreads();
}

// ---------------------------------------------------------------------------
// QKV projection + fused RoPE. grid = (16, 32, 3); z: 0=Q(rope) 1=K(rope) 2=V
// Output layout: [B, H, L, DH]
// ---------------------------------------------------------------------------
__global__ void __launch_bounds__(BDIM)
proj_kernel(const float* __restrict__ X,
            const float* __restrict__ Wq,
            const float* __restrict__ Wk,
            const float* __restrict__ Wv,
            const float* __restrict__ cosT,
            const float* __restrict__ sinT) {
    extern __shared__ float sm[];
    const int z = blockIdx.z;
    const float* W = (z == 0) ? Wq : (z == 1) ? Wk : Wv;
    float* O = (z == 0) ? g_Q : (z == 1) ? g_K : g_V;

    gemm_core(X, W, sm);

    float* cs = sm;
    const int m0 = blockIdx.y * 128;
    const int n0 = blockIdx.x * 128;
    const int h  = n0 / DHc;          // each 128-wide N tile is exactly one head
    const int tid = threadIdx.x;

    if (z < 2) {
        // RoPE on interleaved pairs (2p, 2p+1) within the head
        for (int idx = tid; idx < 128 * 64; idx += BDIM) {
            int r = idx >> 6, p = idx & 63;
            int m = m0 + r;
            int l = m & (Lc - 1);
            int bi = m >> 11;             // m / L
            float t1 = cs[r * 132 + 2 * p];
            float t2 = cs[r * 132 + 2 * p + 1];
            float c = cosT[l * 64 + p];
            float s = sinT[l * 64 + p];
            size_t base = (((size_t)(bi * Hc + h) * Lc + l) * DHc) + 2 * p;
            O[base]     = t1 * c - t2 * s;
            O[base + 1] = t1 * s + t2 * c;
        }
    } else {
        for (int idx = tid; idx < 128 * 128; idx += BDIM) {
            int r = idx >> 7, d = idx & 127;
            int m = m0 + r;
            int l = m & (Lc - 1);
            int bi = m >> 11;
            O[(((size_t)(bi * Hc + h) * Lc + l) * DHc) + d] = cs[r * 132 + d];
        }
    }
}

// ---------------------------------------------------------------------------
// Flash attention (causal), 64-query tile per CTA. grid = (L/64, H, B)
// 2-stage cp.async pipeline on K/V tiles; TF32 WMMA for S and PV.
// Writes to g_A as [B*L, D] with e = h*DH + dh.
// ---------------------------------------------------------------------------
constexpr int KVBUF = 64 * 132;       // 8448 floats per stage buffer

__device__ __forceinline__ void ld_kv_async(const float* __restrict__ Kp,
                                            const float* __restrict__ Vp,
                                            float* Ks, float* Vs, int k0, int tid) {
#pragma unroll
    for (int i = 0; i < 8; i++) {
        int fi = tid + BDIM * i;          // 2048 float4 per matrix
        int r  = fi >> 5;
        int c  = (fi & 31) << 2;
        cp_async16(Ks + r * 132 + c, Kp + (size_t)(k0 + r) * DHc + c);
        cp_async16(Vs + r * 132 + c, Vp + (size_t)(k0 + r) * DHc + c);
    }
}

__global__ void __launch_bounds__(BDIM) attn_kernel() {
    extern __shared__ float sm[];
    float* Qs = sm;                        // [64][132]
    float* KB = Qs + KVBUF;                // 2 x [64][132]
    float* VB = KB + 2 * KVBUF;            // 2 x [64][132]
    float* Ss = VB + 2 * KVBUF;            // [64][68]
    float* Ac = Ss + 64 * 68;              // [64][132]
    float* Ar = Ac + KVBUF;                // [64] alpha
    float* Lr = Ar + 64;                   // [64] l

    const int tid  = threadIdx.x;
    const int warp = tid >> 5;
    const int q0 = blockIdx.x * 64;
    const int h  = blockIdx.y;
    const int bb = blockIdx.z;
    const size_t head_off = ((size_t)(bb * Hc + h) * Lc) * DHc;
    const float* Qp = g_Q + head_off;
    const float* Kp = g_K + head_off;
    const float* Vp = g_V + head_off;
    const float SC = SCALE_C;

    const int nkt = q0 / 64 + 1;          // causal: only tiles with k0 <= q0

    // Kick off K/V tile 0, then load Q + zero accumulator (overlapped)
    ld_kv_async(Kp, Vp, KB, VB, 0, tid);
    cp_commit();
#pragma unroll
    for (int i = 0; i < 8; i++) {
        int fi = tid + BDIM * i;          // 2048 float4
        int r  = fi >> 5;
        int c  = (fi & 31) << 2;
        *(float4*)(Qs + r * 132 + c) = *(const float4*)(Qp + (size_t)(q0 + r) * DHc + c);
        *(float4*)(Ac + r * 132 + c) = make_float4(0.f, 0.f, 0.f, 0.f);
    }
    float mreg = -1e30f, lreg = 0.0f;     // replicated across each quad of threads

    for (int kt = 0; kt < nkt; kt++) {
        const int k0 = kt * 64;
        float* Ks = KB + (kt & 1) * KVBUF;
        float* Vs = VB + (kt & 1) * KVBUF;
        if (kt + 1 < nkt) {
            ld_kv_async(Kp, Vp, KB + ((kt + 1) & 1) * KVBUF, VB + ((kt + 1) & 1) * KVBUF,
                        (kt + 1) * 64, tid);
            cp_commit();
            cp_wait<1>();
        } else {
            cp_wait<0>();
        }
        __syncthreads();                  // K/V tile kt resident; Qs/Ac visible (1st iter)

        // S = Q K^T  (64x64, 16 tiles of 16x16, 2 per warp)
#pragma unroll
        for (int j = 0; j < 2; j++) {
            int t = warp * 2 + j;
            int tm = t >> 2, tn = t & 3;
            wmma::fragment<wmma::accumulator, 16, 16, 8, float> sf;
            wmma::fill_fragment(sf, 0.0f);
#pragma unroll
            for (int kk = 0; kk < 128; kk += 8) {
                wmma::fragment<wmma::matrix_a, 16, 16, 8, wmma::precision::tf32, wmma::row_major> af;
                wmma::fragment<wmma::matrix_b, 16, 16, 8, wmma::precision::tf32, wmma::col_major> bf;
                wmma::load_matrix_sync(af, Qs + (tm * 16) * 132 + kk, 132);
                wmma::load_matrix_sync(bf, Ks + (tn * 16) * 132 + kk, 132);
#pragma unroll
                for (int e = 0; e < af.num_elements; e++) af.x[e] = wmma::__float_to_tf32(af.x[e]);
#pragma unroll
                for (int e = 0; e < bf.num_elements; e++) bf.x[e] = wmma::__float_to_tf32(bf.x[e]);
                wmma::mma_sync(sf, af, bf, sf);
            }
            wmma::store_matrix_sync(Ss + (tm * 16) * 68 + tn * 16, sf, 68, wmma::mem_row_major);
        }
        __syncthreads();

        // Online softmax: 4 threads per row (quad shuffle reduction)
        {
            int row = tid >> 2;
            int sub = tid & 3;
            int q = q0 + row;
            int vis = q - k0;             // columns c <= vis are visible
            float* srow = Ss + row * 68;
            float mx = -1e30f;
#pragma unroll
            for (int c = sub * 16; c < sub * 16 + 16; c++)
                if (c <= vis) mx = fmaxf(mx, srow[c]);
            mx = fmaxf(mx, __shfl_xor_sync(0xffffffffu, mx, 1));
            mx = fmaxf(mx, __shfl_xor_sync(0xffffffffu, mx, 2));
            float mn = fmaxf(mreg, mx * SC);
            float alpha = __expf(mreg - mn);
            float sum = 0.0f;
#pragma unroll
            for (int c = sub * 16; c < sub * 16 + 16; c++) {
                float p = (c <= vis) ? __expf(srow[c] * SC - mn) : 0.0f;
                srow[c] = p;
                sum += p;
            }
            sum += __shfl_xor_sync(0xffffffffu, sum, 1);
            sum += __shfl_xor_sync(0xffffffffu, sum, 2);
            lreg = lreg * alpha + sum;
            mreg = mn;
            if (sub == 0) Ar[row] = alpha;
        }
        __syncthreads();

        // Rescale accumulator rows by alpha
        for (int idx = tid; idx < 64 * 128; idx += BDIM) {
            int r = idx >> 7;
            Ac[r * 132 + (idx & 127)] *= Ar[r];
        }
        __syncthreads();

        // Ac += P * V  (64x128, 32 tiles of 16x16, 4 per warp)
#pragma unroll
        for (int j = 0; j < 4; j++) {
            int t = warp * 4 + j;
            int tm = t >> 3, tn = t & 7;
            wmma::fragment<wmma::accumulator, 16, 16, 8, float> of;
            wmma::load_matrix_sync(of, Ac + (tm * 16) * 132 + tn * 16, 132, wmma::mem_row_major);
#pragma unroll
            for (int kk = 0; kk < 64; kk += 8) {
                wmma::fragment<wmma::matrix_a, 16, 16, 8, wmma::precision::tf32, wmma::row_major> af;
                wmma::fragment<wmma::matrix_b, 16, 16, 8, wmma::precision::tf32, wmma::row_major> bf;
                wmma::load_matrix_sync(af, Ss + (tm * 16) * 68 + kk, 68);
                wmma::load_matrix_sync(bf, Vs + kk * 132 + tn * 16, 132);
#pragma unroll
                for (int e = 0; e < af.num_elements; e++) af.x[e] = wmma::__float_to_tf32(af.x[e]);
#pragma unroll
                for (int e = 0; e < bf.num_elements; e++) bf.x[e] = wmma::__float_to_tf32(bf.x[e]);
                wmma::mma_sync(of, af, bf, of);
            }
            wmma::store_matrix_sync(Ac + (tm * 16) * 132 + tn * 16, of, 132, wmma::mem_row_major);
        }
        __syncthreads();                  // protect Vs/Ss before next prefetch/overwrite
    }

    if ((tid & 3) == 0) Lr[tid >> 2] = lreg;
    __syncthreads();

    // Write normalized output: g_A[b*L + q, h*DH + d]
    for (int idx = tid; idx < 64 * 128; idx += BDIM) {
        int r = idx >> 7, d = idx & 127;
        size_t m = (size_t)bb * Lc + q0 + r;
        g_A[m * Dc + h * DHc + d] = Ac[r * 132 + d] / Lr[r];
    }
}

// ---------------------------------------------------------------------------
// Output projection: out = A * Wo^T. grid = (16, 32)
// ---------------------------------------------------------------------------
__global__ void __launch_bounds__(BDIM)
oproj_kernel(const float* __restrict__ Wo, float* __restrict__ out) {
    extern __shared__ float sm[];
    gemm_core(g_A, Wo, sm);
    float* cs = sm;
    const int m0 = blockIdx.y * 128;
    const int n0 = blockIdx.x * 128;
    const int tid = threadIdx.x;
    for (int idx = tid; idx < 128 * 128; idx += BDIM) {
        int r = idx >> 7, c = idx & 127;
        out[(size_t)(m0 + r) * Dc + n0 + c] = cs[r * 132 + c];
    }
}

// ---------------------------------------------------------------------------
extern "C" void kernel_launch(void* const* d_in, const int* in_sizes, int n_in,
                              void* d_out, int out_size) {
    const float* x    = (const float*)d_in[0];
    // d_in[1] = mask (unused: causal mask applied analytically)
    const float* cosT = (const float*)d_in[2];
    const float* sinT = (const float*)d_in[3];
    const float* wq   = (const float*)d_in[4];
    const float* wk   = (const float*)d_in[5];
    const float* wv   = (const float*)d_in[6];
    const float* wo   = (const float*)d_in[7];
    float* out = (float*)d_out;

    // GEMM smem: max(3-stage pipeline, result tile) = max(6*XBUF, 128*132)
    const int smemG = (2 * NSTG * XBUF) * (int)sizeof(float);                 // 110592 B
    // Attention smem: Qs + 2*KB + 2*VB + Ss + Ac + Ar/Lr
    const int smemA = (6 * KVBUF + 64 * 68 + 128) * (int)sizeof(float);       // 220672 B

    cudaFuncSetAttribute(proj_kernel,  cudaFuncAttributeMaxDynamicSharedMemorySize, smemG);
    cudaFuncSetAttribute(oproj_kernel, cudaFuncAttributeMaxDynamicSharedMemorySize, smemG);
    cudaFuncSetAttribute(attn_kernel,  cudaFuncAttributeMaxDynamicSharedMemorySize, smemA);

    proj_kernel<<<dim3(Dc / 128, (Bc * Lc) / 128, 3), BDIM, smemG>>>(x, wq, wk, wv, cosT, sinT);
    attn_kernel<<<dim3(Lc / 64, Hc, Bc), BDIM, smemA>>>();
    oproj_kernel<<<dim3(Dc / 128, (Bc * Lc) / 128, 1), BDIM, smemG>>>(wo, out);
}

// round 4
// speedup vs baseline: 1.1682x; 1.1682x over previous
#include <cuda_runtime.h>
#include <cuda_bf16.h>
#include <mma.h>

using namespace nvcuda;

// Problem constants
constexpr int Bc  = 2;
constexpr int Lc  = 2048;
constexpr int Dc  = 2048;
constexpr int Hc  = 16;
constexpr int DHc = 128;

constexpr int BDIM = 256;
__device__ __constant__ float SCALE_C = 0.08838834764831845f; // 1/sqrt(128)

// Scratch (static device globals: allocation-free per harness rules)
__device__ float g_Q[(size_t)Bc * Hc * Lc * DHc];
__device__ float g_K[(size_t)Bc * Hc * Lc * DHc];
__device__ float g_V[(size_t)Bc * Hc * Lc * DHc];
__device__ float g_A[(size_t)Bc * Lc * Dc];
// tf32-pre-rounded operands
__device__ float g_Xt[(size_t)Bc * Lc * Dc];
__device__ float g_Wq[(size_t)Dc * Dc];
__device__ float g_Wk[(size_t)Dc * Dc];
__device__ float g_Wv[(size_t)Dc * Dc];
__device__ float g_Wo[(size_t)Dc * Dc];

// ---------------------------------------------------------------------------
// cp.async helpers
// ---------------------------------------------------------------------------
__device__ __forceinline__ void cp_async16(float* smem_dst, const float* gmem_src) {
    unsigned s = (unsigned)__cvta_generic_to_shared(smem_dst);
    asm volatile("cp.async.cg.shared.global [%0], [%1], 16;\n" :: "r"(s), "l"(gmem_src));
}
__device__ __forceinline__ void cp_commit() {
    asm volatile("cp.async.commit_group;\n");
}
template <int N>
__device__ __forceinline__ void cp_wait() {
    asm volatile("cp.async.wait_group %0;\n" :: "n"(N));
}

// ---------------------------------------------------------------------------
// Pre-round inputs to tf32 (removes all per-fragment cvt work in hot loops).
// Flat grid covering x(8.39M) + wq/wk/wv/wo (4×4.19M) elements, float4-wide.
// ---------------------------------------------------------------------------
__global__ void __launch_bounds__(256)
cvt_kernel(const float* __restrict__ x,  const float* __restrict__ wq,
           const float* __restrict__ wk, const float* __restrict__ wv,
           const float* __restrict__ wo) {
    constexpr size_t NX = (size_t)Bc * Lc * Dc;   // 8388608
    constexpr size_t NW = (size_t)Dc * Dc;        // 4194304
    size_t i4 = (size_t)blockIdx.x * 256 + threadIdx.x;   // float4 index
    size_t i = i4 * 4;
    const float* src; float* dst;
    if (i < NX)                { src = x  + i;               dst = g_Xt + i; }
    else if (i < NX + NW)      { src = wq + (i - NX);        dst = g_Wq + (i - NX); }
    else if (i < NX + 2 * NW)  { src = wk + (i - NX - NW);   dst = g_Wk + (i - NX - NW); }
    else if (i < NX + 3 * NW)  { src = wv + (i - NX - 2*NW); dst = g_Wv + (i - NX - 2*NW); }
    else if (i < NX + 4 * NW)  { src = wo + (i - NX - 3*NW); dst = g_Wo + (i - NX - 3*NW); }
    else return;
    float4 v = *(const float4*)src;
    v.x = wmma::__float_to_tf32(v.x);
    v.y = wmma::__float_to_tf32(v.y);
    v.z = wmma::__float_to_tf32(v.z);
    v.w = wmma::__float_to_tf32(v.w);
    *(float4*)dst = v;
}

// ---------------------------------------------------------------------------
// TF32 WMMA GEMM core, 3-stage cp.async pipeline. Operands PRE-ROUNDED.
// Computes a 128x128 tile of C = X * W^T   (K = Dc, both row-major)
// Result left in smem as cs[128][132] (fp32) with trailing __syncthreads().
// blockDim = 256. smem: 6 buffers of [128][36] floats = 110592 B.
// ---------------------------------------------------------------------------
constexpr int XBUF = 128 * 36;   // 4608 floats per stage buffer
constexpr int NSTG = 3;

__device__ __forceinline__ void ld_chunk_async(const float* __restrict__ X,
                                               const float* __restrict__ W,
                                               float* xs, float* ws,
                                               int m0, int n0, int k0, int tid) {
#pragma unroll
    for (int i = 0; i < 4; i++) {
        int fi = tid + BDIM * i;          // 1024 float4 per matrix
        int r  = fi >> 3;                 // 8 float4 per 32-float row
        int c  = (fi & 7) << 2;
        cp_async16(xs + r * 36 + c, X + (size_t)(m0 + r) * Dc + k0 + c);
        cp_async16(ws + r * 36 + c, W + (size_t)(n0 + r) * Dc + k0 + c);
    }
}

__device__ __forceinline__ void gemm_core(const float* __restrict__ X,
                                          const float* __restrict__ W,
                                          float* sm) {
    const int tid = threadIdx.x;
    const int m0 = blockIdx.y * 128;
    const int n0 = blockIdx.x * 128;
    float* xb = sm;                       // NSTG x [128][36]
    float* wb = sm + NSTG * XBUF;         // NSTG x [128][36]
    const int warp = tid >> 5;
    const int wm = warp & 3;              // 4 warps along M (32 rows)
    const int wn = warp >> 2;             // 2 warps along N (64 cols)

    wmma::fragment<wmma::accumulator, 16, 16, 8, float> cf[2][4];
#pragma unroll
    for (int i = 0; i < 2; i++)
#pragma unroll
        for (int j = 0; j < 4; j++)
            wmma::fill_fragment(cf[i][j], 0.0f);

    constexpr int NC = Dc / 32;           // 64 K-chunks
    ld_chunk_async(X, W, xb, wb, m0, n0, 0, tid);
    cp_commit();
    ld_chunk_async(X, W, xb + XBUF, wb + XBUF, m0, n0, 32, tid);
    cp_commit();

    int buf = 0;
    for (int c = 0; c < NC; c++) {
        if (c + 2 < NC) {
            int nb = buf + 2; if (nb >= NSTG) nb -= NSTG;
            ld_chunk_async(X, W, xb + nb * XBUF, wb + nb * XBUF,
                           m0, n0, (c + 2) * 32, tid);
        }
        cp_commit();
        cp_wait<2>();                     // chunk c resident
        __syncthreads();

        float* xs = xb + buf * XBUF;
        float* ws = wb + buf * XBUF;
#pragma unroll
        for (int kk = 0; kk < 32; kk += 8) {
            wmma::fragment<wmma::matrix_a, 16, 16, 8, wmma::precision::tf32, wmma::row_major> af[2];
            wmma::fragment<wmma::matrix_b, 16, 16, 8, wmma::precision::tf32, wmma::col_major> bf[4];
#pragma unroll
            for (int i = 0; i < 2; i++)
                wmma::load_matrix_sync(af[i], xs + (wm * 32 + i * 16) * 36 + kk, 36);
#pragma unroll
            for (int j = 0; j < 4; j++)
                wmma::load_matrix_sync(bf[j], ws + (wn * 64 + j * 16) * 36 + kk, 36);
#pragma unroll
            for (int i = 0; i < 2; i++)
#pragma unroll
                for (int j = 0; j < 4; j++)
                    wmma::mma_sync(cf[i][j], af[i], bf[j], cf[i][j]);
        }
        __syncthreads();
        buf++; if (buf == NSTG) buf = 0;
    }

    float* cs = sm;                       // [128][132], reuses pipeline buffers
#pragma unroll
    for (int i = 0; i < 2; i++)
#pragma unroll
        for (int j = 0; j < 4; j++)
            wmma::store_matrix_sync(cs + (wm * 32 + i * 16) * 132 + wn * 64 + j * 16,
                                    cf[i][j], 132, wmma::mem_row_major);
    __syncthreads();
}

// ---------------------------------------------------------------------------
// QKV projection + fused RoPE. grid = (16, 32, 3); z: 0=Q(rope) 1=K(rope) 2=V
// Outputs tf32-rounded [B, H, L, DH].
// ---------------------------------------------------------------------------
__global__ void __launch_bounds__(BDIM, 2)
proj_kernel(const float* __restrict__ cosT, const float* __restrict__ sinT) {
    extern __shared__ float sm[];
    const int z = blockIdx.z;
    const float* W = (z == 0) ? g_Wq : (z == 1) ? g_Wk : g_Wv;
    float* O = (z == 0) ? g_Q : (z == 1) ? g_K : g_V;

    gemm_core(g_Xt, W, sm);

    float* cs = sm;
    const int m0 = blockIdx.y * 128;
    const int n0 = blockIdx.x * 128;
    const int h  = n0 / DHc;          // each 128-wide N tile is exactly one head
    const int tid = threadIdx.x;

    if (z < 2) {
        // RoPE on interleaved pairs (2p, 2p+1); round result to tf32
        for (int idx = tid; idx < 128 * 64; idx += BDIM) {
            int r = idx >> 6, p = idx & 63;
            int m = m0 + r;
            int l = m & (Lc - 1);
            int bi = m >> 11;
            float t1 = cs[r * 132 + 2 * p];
            float t2 = cs[r * 132 + 2 * p + 1];
            float c = cosT[l * 64 + p];
            float s = sinT[l * 64 + p];
            size_t base = (((size_t)(bi * Hc + h) * Lc + l) * DHc) + 2 * p;
            O[base]     = wmma::__float_to_tf32(t1 * c - t2 * s);
            O[base + 1] = wmma::__float_to_tf32(t1 * s + t2 * c);
        }
    } else {
        for (int idx = tid; idx < 128 * 128; idx += BDIM) {
            int r = idx >> 7, d = idx & 127;
            int m = m0 + r;
            int l = m & (Lc - 1);
            int bi = m >> 11;
            O[(((size_t)(bi * Hc + h) * Lc + l) * DHc) + d] =
                wmma::__float_to_tf32(cs[r * 132 + d]);
        }
    }
}

// ---------------------------------------------------------------------------
// Flash attention (causal), 64-query tile per CTA. grid = (L/64, H, B)
// Q/K/V pre-rounded; P rounded at softmax store; output rounded for oproj.
// ---------------------------------------------------------------------------
constexpr int KVBUF = 64 * 132;       // 8448 floats per stage buffer

__device__ __forceinline__ void ld_kv_async(const float* __restrict__ Kp,
                                            const float* __restrict__ Vp,
                                            float* Ks, float* Vs, int k0, int tid) {
#pragma unroll
    for (int i = 0; i < 8; i++) {
        int fi = tid + BDIM * i;          // 2048 float4 per matrix
        int r  = fi >> 5;
        int c  = (fi & 31) << 2;
        cp_async16(Ks + r * 132 + c, Kp + (size_t)(k0 + r) * DHc + c);
        cp_async16(Vs + r * 132 + c, Vp + (size_t)(k0 + r) * DHc + c);
    }
}

__global__ void __launch_bounds__(BDIM) attn_kernel() {
    extern __shared__ float sm[];
    float* Qs = sm;                        // [64][132]
    float* KB = Qs + KVBUF;                // 2 x [64][132]
    float* VB = KB + 2 * KVBUF;            // 2 x [64][132]
    float* Ss = VB + 2 * KVBUF;            // [64][68]
    float* Ac = Ss + 64 * 68;              // [64][132]
    float* Ar = Ac + KVBUF;                // [64] alpha
    float* Lr = Ar + 64;                   // [64] l

    const int tid  = threadIdx.x;
    const int warp = tid >> 5;
    const int q0 = blockIdx.x * 64;
    const int h  = blockIdx.y;
    const int bb = blockIdx.z;
    const size_t head_off = ((size_t)(bb * Hc + h) * Lc) * DHc;
    const float* Qp = g_Q + head_off;
    const float* Kp = g_K + head_off;
    const float* Vp = g_V + head_off;
    const float SC = SCALE_C;

    const int nkt = q0 / 64 + 1;          // causal: only tiles with k0 <= q0

    ld_kv_async(Kp, Vp, KB, VB, 0, tid);
    cp_commit();
#pragma unroll
    for (int i = 0; i < 8; i++) {
        int fi = tid + BDIM * i;          // 2048 float4
        int r  = fi >> 5;
        int c  = (fi & 31) << 2;
        *(float4*)(Qs + r * 132 + c) = *(const float4*)(Qp + (size_t)(q0 + r) * DHc + c);
        *(float4*)(Ac + r * 132 + c) = make_float4(0.f, 0.f, 0.f, 0.f);
    }
    float mreg = -1e30f, lreg = 0.0f;     // replicated across each quad of threads

    for (int kt = 0; kt < nkt; kt++) {
        const int k0 = kt * 64;
        float* Ks = KB + (kt & 1) * KVBUF;
        float* Vs = VB + (kt & 1) * KVBUF;
        if (kt + 1 < nkt) {
            ld_kv_async(Kp, Vp, KB + ((kt + 1) & 1) * KVBUF, VB + ((kt + 1) & 1) * KVBUF,
                        (kt + 1) * 64, tid);
            cp_commit();
            cp_wait<1>();
        } else {
            cp_wait<0>();
        }
        __syncthreads();                  // K/V tile kt resident; Qs/Ac visible (1st iter)

        // S = Q K^T  (64x64, 16 tiles of 16x16, 2 per warp)
#pragma unroll
        for (int j = 0; j < 2; j++) {
            int t = warp * 2 + j;
            int tm = t >> 2, tn = t & 3;
            wmma::fragment<wmma::accumulator, 16, 16, 8, float> sf;
            wmma::fill_fragment(sf, 0.0f);
#pragma unroll
            for (int kk = 0; kk < 128; kk += 8) {
                wmma::fragment<wmma::matrix_a, 16, 16, 8, wmma::precision::tf32, wmma::row_major> af;
                wmma::fragment<wmma::matrix_b, 16, 16, 8, wmma::precision::tf32, wmma::col_major> bf;
                wmma::load_matrix_sync(af, Qs + (tm * 16) * 132 + kk, 132);
                wmma::load_matrix_sync(bf, Ks + (tn * 16) * 132 + kk, 132);
                wmma::mma_sync(sf, af, bf, sf);
            }
            wmma::store_matrix_sync(Ss + (tm * 16) * 68 + tn * 16, sf, 68, wmma::mem_row_major);
        }
        __syncthreads();

        // Online softmax: 4 threads per row; store tf32-rounded probs
        {
            int row = tid >> 2;
            int sub = tid & 3;
            int q = q0 + row;
            int vis = q - k0;             // columns c <= vis are visible
            float* srow = Ss + row * 68;
            float mx = -1e30f;
#pragma unroll
            for (int c = sub * 16; c < sub * 16 + 16; c++)
                if (c <= vis) mx = fmaxf(mx, srow[c]);
            mx = fmaxf(mx, __shfl_xor_sync(0xffffffffu, mx, 1));
            mx = fmaxf(mx, __shfl_xor_sync(0xffffffffu, mx, 2));
            float mn = fmaxf(mreg, mx * SC);
            float alpha = __expf(mreg - mn);
            float sum = 0.0f;
#pragma unroll
            for (int c = sub * 16; c < sub * 16 + 16; c++) {
                float p = (c <= vis) ? wmma::__float_to_tf32(__expf(srow[c] * SC - mn)) : 0.0f;
                srow[c] = p;
                sum += p;
            }
            sum += __shfl_xor_sync(0xffffffffu, sum, 1);
            sum += __shfl_xor_sync(0xffffffffu, sum, 2);
            lreg = lreg * alpha + sum;
            mreg = mn;
            if (sub == 0) Ar[row] = alpha;
        }
        __syncthreads();

        // Rescale accumulator rows by alpha
        for (int idx = tid; idx < 64 * 128; idx += BDIM) {
            int r = idx >> 7;
            Ac[r * 132 + (idx & 127)] *= Ar[r];
        }
        __syncthreads();

        // Ac += P * V  (64x128, 32 tiles of 16x16, 4 per warp)
#pragma unroll
        for (int j = 0; j < 4; j++) {
            int t = warp * 4 + j;
            int tm = t >> 3, tn = t & 7;
            wmma::fragment<wmma::accumulator, 16, 16, 8, float> of;
            wmma::load_matrix_sync(of, Ac + (tm * 16) * 132 + tn * 16, 132, wmma::mem_row_major);
#pragma unroll
            for (int kk = 0; kk < 64; kk += 8) {
                wmma::fragment<wmma::matrix_a, 16, 16, 8, wmma::precision::tf32, wmma::row_major> af;
                wmma::fragment<wmma::matrix_b, 16, 16, 8, wmma::precision::tf32, wmma::row_major> bf;
                wmma::load_matrix_sync(af, Ss + (tm * 16) * 68 + kk, 68);
                wmma::load_matrix_sync(bf, Vs + kk * 132 + tn * 16, 132);
                wmma::mma_sync(of, af, bf, of);
            }
            wmma::store_matrix_sync(Ac + (tm * 16) * 132 + tn * 16, of, 132, wmma::mem_row_major);
        }
        __syncthreads();                  // protect Vs/Ss before next prefetch/overwrite
    }

    if ((tid & 3) == 0) Lr[tid >> 2] = lreg;
    __syncthreads();

    // Write normalized, tf32-rounded output: g_A[b*L + q, h*DH + d]
    for (int idx = tid; idx < 64 * 128; idx += BDIM) {
        int r = idx >> 7, d = idx & 127;
        size_t m = (size_t)bb * Lc + q0 + r;
        g_A[m * Dc + h * DHc + d] = wmma::__float_to_tf32(Ac[r * 132 + d] / Lr[r]);
    }
}

// ---------------------------------------------------------------------------
// Output projection: out = A * Wo^T. grid = (16, 32)
// ---------------------------------------------------------------------------
__global__ void __launch_bounds__(BDIM, 2)
oproj_kernel(float* __restrict__ out) {
    extern __shared__ float sm[];
    gemm_core(g_A, g_Wo, sm);
    float* cs = sm;
    const int m0 = blockIdx.y * 128;
    const int n0 = blockIdx.x * 128;
    const int tid = threadIdx.x;
    for (int idx = tid; idx < 128 * 128; idx += BDIM) {
        int r = idx >> 7, c = idx & 127;
        out[(size_t)(m0 + r) * Dc + n0 + c] = cs[r * 132 + c];
    }
}

// ---------------------------------------------------------------------------
extern "C" void kernel_launch(void* const* d_in, const int* in_sizes, int n_in,
                              void* d_out, int out_size) {
    const float* x    = (const float*)d_in[0];
    // d_in[1] = mask (unused: causal mask applied analytically)
    const float* cosT = (const float*)d_in[2];
    const float* sinT = (const float*)d_in[3];
    const float* wq   = (const float*)d_in[4];
    const float* wk   = (const float*)d_in[5];
    const float* wv   = (const float*)d_in[6];
    const float* wo   = (const float*)d_in[7];
    float* out = (float*)d_out;

    const int smemG = (2 * NSTG * XBUF) * (int)sizeof(float);                 // 110592 B
    const int smemA = (6 * KVBUF + 64 * 68 + 128) * (int)sizeof(float);       // 220672 B

    cudaFuncSetAttribute(proj_kernel,  cudaFuncAttributeMaxDynamicSharedMemorySize, smemG);
    cudaFuncSetAttribute(oproj_kernel, cudaFuncAttributeMaxDynamicSharedMemorySize, smemG);
    cudaFuncSetAttribute(attn_kernel,  cudaFuncAttributeMaxDynamicSharedMemorySize, smemA);

    // 25.2M elements / 4 per thread / 256 per block
    constexpr size_t NTOT = (size_t)Bc * Lc * Dc + 4 * (size_t)Dc * Dc;
    cvt_kernel<<<(unsigned)((NTOT / 4 + 255) / 256), 256>>>(x, wq, wk, wv, wo);
    proj_kernel<<<dim3(Dc / 128, (Bc * Lc) / 128, 3), BDIM, smemG>>>(cosT, sinT);
    attn_kernel<<<dim3(Lc / 64, Hc, Bc), BDIM, smemA>>>();
    oproj_kernel<<<dim3(Dc / 128, (Bc * Lc) / 128, 1), BDIM, smemG>>>(out);
}

// round 5
// speedup vs baseline: 1.2764x; 1.0926x over previous
#include <cuda_runtime.h>
#include <cuda_bf16.h>
#include <mma.h>

using namespace nvcuda;

// Problem constants
constexpr int Bc  = 2;
constexpr int Lc  = 2048;
constexpr int Dc  = 2048;
constexpr int Hc  = 16;
constexpr int DHc = 128;

constexpr int BDIM = 256;
__device__ __constant__ float SCALE_C = 0.08838834764831845f; // 1/sqrt(128)

// Scratch (static device globals: allocation-free per harness rules)
__device__ float g_Q[(size_t)Bc * Hc * Lc * DHc];
__device__ float g_K[(size_t)Bc * Hc * Lc * DHc];
__device__ float g_V[(size_t)Bc * Hc * Lc * DHc];
__device__ float g_A[(size_t)Bc * Lc * Dc];
// tf32-pre-rounded operands
__device__ float g_Xt[(size_t)Bc * Lc * Dc];
__device__ float g_Wq[(size_t)Dc * Dc];
__device__ float g_Wk[(size_t)Dc * Dc];
__device__ float g_Wv[(size_t)Dc * Dc];
__device__ float g_Wo[(size_t)Dc * Dc];

// ---------------------------------------------------------------------------
// cp.async helpers
// ---------------------------------------------------------------------------
__device__ __forceinline__ void cp_async16(float* smem_dst, const float* gmem_src) {
    unsigned s = (unsigned)__cvta_generic_to_shared(smem_dst);
    asm volatile("cp.async.cg.shared.global [%0], [%1], 16;\n" :: "r"(s), "l"(gmem_src));
}
__device__ __forceinline__ void cp_commit() {
    asm volatile("cp.async.commit_group;\n");
}
template <int N>
__device__ __forceinline__ void cp_wait() {
    asm volatile("cp.async.wait_group %0;\n" :: "n"(N));
}

// ---------------------------------------------------------------------------
// Pre-round inputs to tf32.
// ---------------------------------------------------------------------------
__global__ void __launch_bounds__(256)
cvt_kernel(const float* __restrict__ x,  const float* __restrict__ wq,
           const float* __restrict__ wk, const float* __restrict__ wv,
           const float* __restrict__ wo) {
    constexpr size_t NX = (size_t)Bc * Lc * Dc;   // 8388608
    constexpr size_t NW = (size_t)Dc * Dc;        // 4194304
    size_t i4 = (size_t)blockIdx.x * 256 + threadIdx.x;   // float4 index
    size_t i = i4 * 4;
    const float* src; float* dst;
    if (i < NX)                { src = x  + i;               dst = g_Xt + i; }
    else if (i < NX + NW)      { src = wq + (i - NX);        dst = g_Wq + (i - NX); }
    else if (i < NX + 2 * NW)  { src = wk + (i - NX - NW);   dst = g_Wk + (i - NX - NW); }
    else if (i < NX + 3 * NW)  { src = wv + (i - NX - 2*NW); dst = g_Wv + (i - NX - 2*NW); }
    else if (i < NX + 4 * NW)  { src = wo + (i - NX - 3*NW); dst = g_Wo + (i - NX - 3*NW); }
    else return;
    float4 v = *(const float4*)src;
    v.x = wmma::__float_to_tf32(v.x);
    v.y = wmma::__float_to_tf32(v.y);
    v.z = wmma::__float_to_tf32(v.z);
    v.w = wmma::__float_to_tf32(v.w);
    *(float4*)dst = v;
}

// ---------------------------------------------------------------------------
// TF32 WMMA GEMM core, 3-stage cp.async pipeline, ONE barrier per K-chunk.
// Computes a 128x128 tile of C = X * W^T (K = Dc). Result in cs[128][132].
// ---------------------------------------------------------------------------
constexpr int XBUF = 128 * 36;   // 4608 floats per stage buffer
constexpr int NSTG = 3;

__device__ __forceinline__ void ld_chunk_async(const float* __restrict__ X,
                                               const float* __restrict__ W,
                                               float* xs, float* ws,
                                               int m0, int n0, int k0, int tid) {
#pragma unroll
    for (int i = 0; i < 4; i++) {
        int fi = tid + BDIM * i;          // 1024 float4 per matrix
        int r  = fi >> 3;                 // 8 float4 per 32-float row
        int c  = (fi & 7) << 2;
        cp_async16(xs + r * 36 + c, X + (size_t)(m0 + r) * Dc + k0 + c);
        cp_async16(ws + r * 36 + c, W + (size_t)(n0 + r) * Dc + k0 + c);
    }
}

__device__ __forceinline__ void gemm_core(const float* __restrict__ X,
                                          const float* __restrict__ W,
                                          float* sm) {
    const int tid = threadIdx.x;
    const int m0 = blockIdx.y * 128;
    const int n0 = blockIdx.x * 128;
    float* xb = sm;                       // NSTG x [128][36]
    float* wb = sm + NSTG * XBUF;         // NSTG x [128][36]
    const int warp = tid >> 5;
    const int wm = warp & 3;              // 4 warps along M (32 rows)
    const int wn = warp >> 2;             // 2 warps along N (64 cols)

    wmma::fragment<wmma::accumulator, 16, 16, 8, float> cf[2][4];
#pragma unroll
    for (int i = 0; i < 2; i++)
#pragma unroll
        for (int j = 0; j < 4; j++)
            wmma::fill_fragment(cf[i][j], 0.0f);

    constexpr int NC = Dc / 32;           // 64 K-chunks
    ld_chunk_async(X, W, xb, wb, m0, n0, 0, tid);
    cp_commit();
    ld_chunk_async(X, W, xb + XBUF, wb + XBUF, m0, n0, 32, tid);
    cp_commit();

    int buf = 0;
    for (int c = 0; c < NC; c++) {
        cp_wait<1>();                     // chunk c landed (c+1 may be in flight)
        __syncthreads();                  // chunk c visible; buffer (c+2)%3 free
        if (c + 2 < NC) {                 // prefetch chunk c+2 (after barrier!)
            int nb = buf + 2; if (nb >= NSTG) nb -= NSTG;
            ld_chunk_async(X, W, xb + nb * XBUF, wb + nb * XBUF,
                           m0, n0, (c + 2) * 32, tid);
        }
        cp_commit();                      // always commit to keep group count exact

        float* xs = xb + buf * XBUF;
        float* ws = wb + buf * XBUF;
#pragma unroll
        for (int kk = 0; kk < 32; kk += 8) {
            wmma::fragment<wmma::matrix_a, 16, 16, 8, wmma::precision::tf32, wmma::row_major> af[2];
            wmma::fragment<wmma::matrix_b, 16, 16, 8, wmma::precision::tf32, wmma::col_major> bf[4];
#pragma unroll
            for (int i = 0; i < 2; i++)
                wmma::load_matrix_sync(af[i], xs + (wm * 32 + i * 16) * 36 + kk, 36);
#pragma unroll
            for (int j = 0; j < 4; j++)
                wmma::load_matrix_sync(bf[j], ws + (wn * 64 + j * 16) * 36 + kk, 36);
#pragma unroll
            for (int i = 0; i < 2; i++)
#pragma unroll
                for (int j = 0; j < 4; j++)
                    wmma::mma_sync(cf[i][j], af[i], bf[j], cf[i][j]);
        }
        buf++; if (buf == NSTG) buf = 0;
    }
    __syncthreads();                      // done with all buffers

    float* cs = sm;                       // [128][132], reuses pipeline buffers
#pragma unroll
    for (int i = 0; i < 2; i++)
#pragma unroll
        for (int j = 0; j < 4; j++)
            wmma::store_matrix_sync(cs + (wm * 32 + i * 16) * 132 + wn * 64 + j * 16,
                                    cf[i][j], 132, wmma::mem_row_major);
    __syncthreads();
}

// ---------------------------------------------------------------------------
// QKV projection + fused RoPE. grid = (16, 32, 3)
// ---------------------------------------------------------------------------
__global__ void __launch_bounds__(BDIM, 2)
proj_kernel(const float* __restrict__ cosT, const float* __restrict__ sinT) {
    extern __shared__ float sm[];
    const int z = blockIdx.z;
    const float* W = (z == 0) ? g_Wq : (z == 1) ? g_Wk : g_Wv;
    float* O = (z == 0) ? g_Q : (z == 1) ? g_K : g_V;

    gemm_core(g_Xt, W, sm);

    float* cs = sm;
    const int m0 = blockIdx.y * 128;
    const int n0 = blockIdx.x * 128;
    const int h  = n0 / DHc;
    const int tid = threadIdx.x;

    if (z < 2) {
        for (int idx = tid; idx < 128 * 64; idx += BDIM) {
            int r = idx >> 6, p = idx & 63;
            int m = m0 + r;
            int l = m & (Lc - 1);
            int bi = m >> 11;
            float t1 = cs[r * 132 + 2 * p];
            float t2 = cs[r * 132 + 2 * p + 1];
            float c = cosT[l * 64 + p];
            float s = sinT[l * 64 + p];
            size_t base = (((size_t)(bi * Hc + h) * Lc + l) * DHc) + 2 * p;
            O[base]     = wmma::__float_to_tf32(t1 * c - t2 * s);
            O[base + 1] = wmma::__float_to_tf32(t1 * s + t2 * c);
        }
    } else {
        for (int idx = tid; idx < 128 * 128; idx += BDIM) {
            int r = idx >> 7, d = idx & 127;
            int m = m0 + r;
            int l = m & (Lc - 1);
            int bi = m >> 11;
            O[(((size_t)(bi * Hc + h) * Lc + l) * DHc) + d] =
                wmma::__float_to_tf32(cs[r * 132 + d]);
        }
    }
}

// ---------------------------------------------------------------------------
// Flash attention (causal), 64-query tile per CTA, grid = (L/64, H, B).
// Persistent register PV accumulators; row-index fragment for exact row IDs;
// 3 barriers per KV tile; reversed tile order for load balance.
// ---------------------------------------------------------------------------
constexpr int KVBUF = 64 * 132;

__device__ __forceinline__ void ld_kv_async(const float* __restrict__ Kp,
                                            const float* __restrict__ Vp,
                                            float* Ks, float* Vs, int k0, int tid) {
#pragma unroll
    for (int i = 0; i < 8; i++) {
        int fi = tid + BDIM * i;
        int r  = fi >> 5;
        int c  = (fi & 31) << 2;
        cp_async16(Ks + r * 132 + c, Kp + (size_t)(k0 + r) * DHc + c);
        cp_async16(Vs + r * 132 + c, Vp + (size_t)(k0 + r) * DHc + c);
    }
}

__global__ void __launch_bounds__(BDIM) attn_kernel() {
    extern __shared__ float sm[];
    float* Qs = sm;                        // [64][132]
    float* KB = Qs + KVBUF;                // 2 x [64][132]
    float* VB = KB + 2 * KVBUF;            // 2 x [64][132]
    float* Ss = VB + 2 * KVBUF;            // [64][68]
    float* Ac = Ss + 64 * 68;              // [64][132] (epilogue only)
    float* Ar = Ac + KVBUF;                // [64] alpha
    float* Lr = Ar + 64;                   // [64] l

    const int tid  = threadIdx.x;
    const int warp = tid >> 5;
    // Reversed: heaviest (largest q0) tiles get the lowest blockIdx.x
    const int q0 = (int)(gridDim.x - 1 - blockIdx.x) * 64;
    const int h  = blockIdx.y;
    const int bb = blockIdx.z;
    const size_t head_off = ((size_t)(bb * Hc + h) * Lc) * DHc;
    const float* Qp = g_Q + head_off;
    const float* Kp = g_K + head_off;
    const float* Vp = g_V + head_off;
    const float SC = SCALE_C;

    const int nkt = q0 / 64 + 1;

    // PV warp tiling: warp owns rows [tm*16, tm*16+16), cols (warp&1)*64 + j*16
    const int tm = warp >> 1;

    ld_kv_async(Kp, Vp, KB, VB, 0, tid);
    cp_commit();

    // Row-index pattern: Ss[r][c] = r for a 16x16 tile, then load as accumulator
    // fragment to learn each element's row at runtime (no layout assumptions).
    if (tid < 256) Ss[(tid >> 4) * 68 + (tid & 15)] = (float)(tid >> 4);
#pragma unroll
    for (int i = 0; i < 8; i++) {
        int fi = tid + BDIM * i;
        int r  = fi >> 5;
        int c  = (fi & 31) << 2;
        *(float4*)(Qs + r * 132 + c) = *(const float4*)(Qp + (size_t)(q0 + r) * DHc + c);
    }
    __syncthreads();
    wmma::fragment<wmma::accumulator, 16, 16, 8, float> rowf;
    wmma::load_matrix_sync(rowf, Ss, 68, wmma::mem_row_major);

    wmma::fragment<wmma::accumulator, 16, 16, 8, float> of[4];
#pragma unroll
    for (int j = 0; j < 4; j++) wmma::fill_fragment(of[j], 0.0f);

    float mreg = -1e30f, lreg = 0.0f;     // per-quad replicated

    for (int kt = 0; kt < nkt; kt++) {
        const int k0 = kt * 64;
        float* Ks = KB + (kt & 1) * KVBUF;
        float* Vs = VB + (kt & 1) * KVBUF;

        cp_wait<0>();                     // tile kt resident (kt+1 not yet issued)
        __syncthreads();                  // visible to all; prev PV / rowf load done
        if (kt + 1 < nkt) {
            ld_kv_async(Kp, Vp, KB + ((kt + 1) & 1) * KVBUF, VB + ((kt + 1) & 1) * KVBUF,
                        (kt + 1) * 64, tid);
        }
        cp_commit();

        // S = Q K^T  (64x64, 2 tiles of 16x16 per warp)
#pragma unroll
        for (int j = 0; j < 2; j++) {
            int t = warp * 2 + j;
            int stm = t >> 2, stn = t & 3;
            wmma::fragment<wmma::accumulator, 16, 16, 8, float> sf;
            wmma::fill_fragment(sf, 0.0f);
#pragma unroll
            for (int kk = 0; kk < 128; kk += 8) {
                wmma::fragment<wmma::matrix_a, 16, 16, 8, wmma::precision::tf32, wmma::row_major> af;
                wmma::fragment<wmma::matrix_b, 16, 16, 8, wmma::precision::tf32, wmma::col_major> bf;
                wmma::load_matrix_sync(af, Qs + (stm * 16) * 132 + kk, 132);
                wmma::load_matrix_sync(bf, Ks + (stn * 16) * 132 + kk, 132);
                wmma::mma_sync(sf, af, bf, sf);
            }
            wmma::store_matrix_sync(Ss + (stm * 16) * 68 + stn * 16, sf, 68, wmma::mem_row_major);
        }
        __syncthreads();

        // Online softmax: 4 threads per row
        {
            int row = tid >> 2;
            int sub = tid & 3;
            int q = q0 + row;
            int vis = q - k0;
            float* srow = Ss + row * 68;
            float mx = -1e30f;
#pragma unroll
            for (int c = sub * 16; c < sub * 16 + 16; c++)
                if (c <= vis) mx = fmaxf(mx, srow[c]);
            mx = fmaxf(mx, __shfl_xor_sync(0xffffffffu, mx, 1));
            mx = fmaxf(mx, __shfl_xor_sync(0xffffffffu, mx, 2));
            float mn = fmaxf(mreg, mx * SC);
            float alpha = __expf(mreg - mn);
            float sum = 0.0f;
#pragma unroll
            for (int c = sub * 16; c < sub * 16 + 16; c++) {
                float p = (c <= vis) ? wmma::__float_to_tf32(__expf(srow[c] * SC - mn)) : 0.0f;
                srow[c] = p;
                sum += p;
            }
            sum += __shfl_xor_sync(0xffffffffu, sum, 1);
            sum += __shfl_xor_sync(0xffffffffu, sum, 2);
            lreg = lreg * alpha + sum;
            mreg = mn;
            if (sub == 0) Ar[row] = alpha;
        }
        __syncthreads();

        // Rescale persistent accumulators by per-row alpha, then of += P*V
        {
            float av[8];
#pragma unroll
            for (int e = 0; e < 8; e++)
                av[e] = Ar[tm * 16 + (int)rowf.x[e]];
#pragma unroll
            for (int j = 0; j < 4; j++)
#pragma unroll
                for (int e = 0; e < 8; e++)
                    of[j].x[e] *= av[e];
        }
#pragma unroll
        for (int j = 0; j < 4; j++) {
            int tn = (warp & 1) * 4 + j;
#pragma unroll
            for (int kk = 0; kk < 64; kk += 8) {
                wmma::fragment<wmma::matrix_a, 16, 16, 8, wmma::precision::tf32, wmma::row_major> af;
                wmma::fragment<wmma::matrix_b, 16, 16, 8, wmma::precision::tf32, wmma::row_major> bf;
                wmma::load_matrix_sync(af, Ss + (tm * 16) * 68 + kk, 68);
                wmma::load_matrix_sync(bf, Vs + kk * 132 + tn * 16, 132);
                wmma::mma_sync(of[j], af, bf, of[j]);
            }
        }
    }

    // Epilogue: dump accumulators + l to smem, normalize, write out
#pragma unroll
    for (int j = 0; j < 4; j++) {
        int tn = (warp & 1) * 4 + j;
        wmma::store_matrix_sync(Ac + (tm * 16) * 132 + tn * 16, of[j], 132, wmma::mem_row_major);
    }
    if ((tid & 3) == 0) Lr[tid >> 2] = lreg;
    __syncthreads();

    for (int idx = tid; idx < 64 * 128; idx += BDIM) {
        int r = idx >> 7, d = idx & 127;
        size_t m = (size_t)bb * Lc + q0 + r;
        g_A[m * Dc + h * DHc + d] = wmma::__float_to_tf32(Ac[r * 132 + d] / Lr[r]);
    }
}

// ---------------------------------------------------------------------------
// Output projection: out = A * Wo^T. grid = (16, 32)
// ---------------------------------------------------------------------------
__global__ void __launch_bounds__(BDIM, 2)
oproj_kernel(float* __restrict__ out) {
    extern __shared__ float sm[];
    gemm_core(g_A, g_Wo, sm);
    float* cs = sm;
    const int m0 = blockIdx.y * 128;
    const int n0 = blockIdx.x * 128;
    const int tid = threadIdx.x;
    for (int idx = tid; idx < 128 * 128; idx += BDIM) {
        int r = idx >> 7, c = idx & 127;
        out[(size_t)(m0 + r) * Dc + n0 + c] = cs[r * 132 + c];
    }
}

// ---------------------------------------------------------------------------
extern "C" void kernel_launch(void* const* d_in, const int* in_sizes, int n_in,
                              void* d_out, int out_size) {
    const float* x    = (const float*)d_in[0];
    const float* cosT = (const float*)d_in[2];
    const float* sinT = (const float*)d_in[3];
    const float* wq   = (const float*)d_in[4];
    const float* wk   = (const float*)d_in[5];
    const float* wv   = (const float*)d_in[6];
    const float* wo   = (const float*)d_in[7];
    float* out = (float*)d_out;

    const int smemG = (2 * NSTG * XBUF) * (int)sizeof(float);                 // 110592 B
    const int smemA = (6 * KVBUF + 64 * 68 + 128) * (int)sizeof(float);       // 220672 B

    cudaFuncSetAttribute(proj_kernel,  cudaFuncAttributeMaxDynamicSharedMemorySize, smemG);
    cudaFuncSetAttribute(oproj_kernel, cudaFuncAttributeMaxDynamicSharedMemorySize, smemG);
    cudaFuncSetAttribute(attn_kernel,  cudaFuncAttributeMaxDynamicSharedMemorySize, smemA);

    constexpr size_t NTOT = (size_t)Bc * Lc * Dc + 4 * (size_t)Dc * Dc;
    cvt_kernel<<<(unsigned)((NTOT / 4 + 255) / 256), 256>>>(x, wq, wk, wv, wo);
    proj_kernel<<<dim3(Dc / 128, (Bc * Lc) / 128, 3), BDIM, smemG>>>(cosT, sinT);
    attn_kernel<<<dim3(Lc / 64, Hc, Bc), BDIM, smemA>>>();
    oproj_kernel<<<dim3(Dc / 128, (Bc * Lc) / 128, 1), BDIM, smemG>>>(out);
}

// round 14
// speedup vs baseline: 4.4156x; 3.4595x over previous
#include <cuda_runtime.h>
#include <cuda_fp16.h>
#include <mma.h>
#include <cstdint>

using namespace nvcuda;

// Problem constants
constexpr int Bc  = 2;
constexpr int Lc  = 2048;
constexpr int Dc  = 2048;
constexpr int Hc  = 16;
constexpr int DHc = 128;

constexpr int BDIM = 256;
__device__ __constant__ float SCALE_C = 0.08838834764831845f; // 1/sqrt(128)

// Scratch (static device globals: allocation-free per harness rules), fp16
__device__ __half g_Qh[(size_t)Bc * Hc * Lc * DHc];
__device__ __half g_Kh[(size_t)Bc * Hc * Lc * DHc];
__device__ __half g_Vh[(size_t)Bc * Hc * Lc * DHc];
__device__ __half g_Ah[(size_t)Bc * Lc * Dc];
__device__ __half g_Xh[(size_t)Bc * Lc * Dc];
__device__ __half g_Wqh[(size_t)Dc * Dc];
__device__ __half g_Wkh[(size_t)Dc * Dc];
__device__ __half g_Wvh[(size_t)Dc * Dc];
__device__ __half g_Woh[(size_t)Dc * Dc];

// ---------------------------------------------------------------------------
// cp.async helpers
// ---------------------------------------------------------------------------
__device__ __forceinline__ void cp_async16(void* smem_dst, const void* gmem_src) {
    unsigned s = (unsigned)__cvta_generic_to_shared(smem_dst);
    asm volatile("cp.async.cg.shared.global [%0], [%1], 16;\n" :: "r"(s), "l"(gmem_src));
}
__device__ __forceinline__ void cp_commit() {
    asm volatile("cp.async.commit_group;\n");
}
template <int N>
__device__ __forceinline__ void cp_wait() {
    asm volatile("cp.async.wait_group %0;\n" :: "n"(N));
}

// ---------------------------------------------------------------------------
// Convert inputs to fp16 (same 10-bit mantissa as tf32 at these magnitudes).
// 8 elements per thread.
// ---------------------------------------------------------------------------
__global__ void __launch_bounds__(256)
cvt_kernel(const float* __restrict__ x,  const float* __restrict__ wq,
           const float* __restrict__ wk, const float* __restrict__ wv,
           const float* __restrict__ wo) {
    constexpr size_t NX = (size_t)Bc * Lc * Dc;   // 8388608
    constexpr size_t NW = (size_t)Dc * Dc;        // 4194304
    size_t i = ((size_t)blockIdx.x * 256 + threadIdx.x) * 8;
    const float* src; __half* dst;
    if (i < NX)                { src = x  + i;               dst = g_Xh  + i; }
    else if (i < NX + NW)      { src = wq + (i - NX);        dst = g_Wqh + (i - NX); }
    else if (i < NX + 2 * NW)  { src = wk + (i - NX - NW);   dst = g_Wkh + (i - NX - NW); }
    else if (i < NX + 3 * NW)  { src = wv + (i - NX - 2*NW); dst = g_Wvh + (i - NX - 2*NW); }
    else if (i < NX + 4 * NW)  { src = wo + (i - NX - 3*NW); dst = g_Woh + (i - NX - 3*NW); }
    else return;
    float4 a = ((const float4*)src)[0];
    float4 b = ((const float4*)src)[1];
    __half2 h0 = __floats2half2_rn(a.x, a.y);
    __half2 h1 = __floats2half2_rn(a.z, a.w);
    __half2 h2 = __floats2half2_rn(b.x, b.y);
    __half2 h3 = __floats2half2_rn(b.z, b.w);
    uint4 packed;
    packed.x = *(uint32_t*)&h0; packed.y = *(uint32_t*)&h1;
    packed.z = *(uint32_t*)&h2; packed.w = *(uint32_t*)&h3;
    *(uint4*)dst = packed;
}

// ---------------------------------------------------------------------------
// fp16 WMMA GEMM core, 3-stage cp.async pipeline, one barrier per K-chunk.
// 128x128 tile of C = X * W^T (K = Dc), fp32 accumulate.
// smem: 6 half buffers [128][40] (10240 B each, 61440 total); result tile
// cs[128][132] fp32 (67584 B) reuses the region. smemG = 67584.
// ---------------------------------------------------------------------------
constexpr int HST   = 40;                 // half stride (mult of 8)
constexpr int HBUFB = 128 * HST * 2;      // 10240 bytes per stage buffer
constexpr int NSTG  = 3;
constexpr int NC_H  = Dc / 32;            // 64 chunks of K=32

__device__ __forceinline__ void ld_chunk_h(const __half* __restrict__ X,
                                           const __half* __restrict__ W,
                                           char* xs, char* ws,
                                           int m0, int n0, int k0, int tid) {
#pragma unroll
    for (int i = 0; i < 2; i++) {
        int fi = tid + BDIM * i;          // 512 float4 per matrix (128 rows x 4)
        int r  = fi >> 2;                 // row 0..127
        int c8 = (fi & 3) * 8;            // half col 0,8,16,24
        cp_async16(xs + (r * HST + c8) * 2, X + (size_t)(m0 + r) * Dc + k0 + c8);
        cp_async16(ws + (r * HST + c8) * 2, W + (size_t)(n0 + r) * Dc + k0 + c8);
    }
}

__device__ __forceinline__ void gemm_core_h(const __half* __restrict__ X,
                                            const __half* __restrict__ W,
                                            char* smc) {
    const int tid = threadIdx.x;
    const int m0 = blockIdx.y * 128;
    const int n0 = blockIdx.x * 128;
    char* xb = smc;                       // 3 x [128][40] half
    char* wb = smc + NSTG * HBUFB;        // 3 x [128][40] half
    const int warp = tid >> 5;
    const int wm = warp & 3;              // 4 warps along M (32 rows)
    const int wn = warp >> 2;             // 2 warps along N (64 cols)

    wmma::fragment<wmma::accumulator, 16, 16, 16, float> cf[2][4];
#pragma unroll
    for (int i = 0; i < 2; i++)
#pragma unroll
        for (int j = 0; j < 4; j++)
            wmma::fill_fragment(cf[i][j], 0.0f);

    ld_chunk_h(X, W, xb, wb, m0, n0, 0, tid);
    cp_commit();
    ld_chunk_h(X, W, xb + HBUFB, wb + HBUFB, m0, n0, 32, tid);
    cp_commit();

    int buf = 0;
    for (int c = 0; c < NC_H; c++) {
        cp_wait<1>();                     // chunk c landed
        __syncthreads();                  // visible; buffer (c+2)%3 free
        if (c + 2 < NC_H) {
            int nb = buf + 2; if (nb >= NSTG) nb -= NSTG;
            ld_chunk_h(X, W, xb + nb * HBUFB, wb + nb * HBUFB,
                       m0, n0, (c + 2) * 32, tid);
        }
        cp_commit();                      // keep group count exact

        const __half* xs = (const __half*)(xb + buf * HBUFB);
        const __half* ws = (const __half*)(wb + buf * HBUFB);
#pragma unroll
        for (int kk = 0; kk < 32; kk += 16) {
            wmma::fragment<wmma::matrix_a, 16, 16, 16, __half, wmma::row_major> af[2];
            wmma::fragment<wmma::matrix_b, 16, 16, 16, __half, wmma::col_major> bf[4];
#pragma unroll
            for (int i = 0; i < 2; i++)
                wmma::load_matrix_sync(af[i], xs + (wm * 32 + i * 16) * HST + kk, HST);
#pragma unroll
            for (int j = 0; j < 4; j++)
                wmma::load_matrix_sync(bf[j], ws + (wn * 64 + j * 16) * HST + kk, HST);
#pragma unroll
            for (int i = 0; i < 2; i++)
#pragma unroll
                for (int j = 0; j < 4; j++)
                    wmma::mma_sync(cf[i][j], af[i], bf[j], cf[i][j]);
        }
        buf++; if (buf == NSTG) buf = 0;
    }
    __syncthreads();

    float* cs = (float*)smc;              // [128][132]
#pragma unroll
    for (int i = 0; i < 2; i++)
#pragma unroll
        for (int j = 0; j < 4; j++)
            wmma::store_matrix_sync(cs + (wm * 32 + i * 16) * 132 + wn * 64 + j * 16,
                                    cf[i][j], 132, wmma::mem_row_major);
    __syncthreads();
}

// ---------------------------------------------------------------------------
// QKV projection + fused RoPE. grid = (16, 32, 3); outputs fp16 [B,H,L,DH].
// ---------------------------------------------------------------------------
__global__ void __launch_bounds__(BDIM, 2)
proj_kernel(const float* __restrict__ cosT, const float* __restrict__ sinT) {
    extern __shared__ __align__(16) char smc[];
    const int z = blockIdx.z;
    const __half* W = (z == 0) ? g_Wqh : (z == 1) ? g_Wkh : g_Wvh;
    __half* O = (z == 0) ? g_Qh : (z == 1) ? g_Kh : g_Vh;

    gemm_core_h(g_Xh, W, smc);

    float* cs = (float*)smc;
    const int m0 = blockIdx.y * 128;
    const int n0 = blockIdx.x * 128;
    const int h  = n0 / DHc;              // each 128-wide N tile is one head
    const int tid = threadIdx.x;

    if (z < 2) {
        for (int idx = tid; idx < 128 * 64; idx += BDIM) {
            int r = idx >> 6, p = idx & 63;
            int m = m0 + r;
            int l = m & (Lc - 1);
            int bi = m >> 11;
            float t1 = cs[r * 132 + 2 * p];
            float t2 = cs[r * 132 + 2 * p + 1];
            float c = cosT[l * 64 + p];
            float s = sinT[l * 64 + p];
            size_t base = (((size_t)(bi * Hc + h) * Lc + l) * DHc) + 2 * p;
            O[base]     = __float2half(t1 * c - t2 * s);
            O[base + 1] = __float2half(t1 * s + t2 * c);
        }
    } else {
        for (int idx = tid; idx < 128 * 128; idx += BDIM) {
            int r = idx >> 7, d = idx & 127;
            int m = m0 + r;
            int l = m & (Lc - 1);
            int bi = m >> 11;
            O[(((size_t)(bi * Hc + h) * Lc + l) * DHc) + d] = __float2half(cs[r * 132 + d]);
        }
    }
}

// ---------------------------------------------------------------------------
// Flash attention (causal), fp16 operands / fp32 softmax+accum.
// 64-query tile per CTA, grid = (L/64, H, B), reversed tile order.
// smem layout (bytes):
//   Qs  half[64][136]  @0       (17408)
//   KB  2x half[64][136] @17408 (34816)
//   VB  2x half[64][136] @52224 (34816)
//   Ss  float[64][68]  @87040   (17408)
//   Ps  half[64][72]   @104448  (9216)
//   Ac  float[64][132] @113664  (33792)
//   Ar  float[64]      @147456, Lr float[64] @147712 -> total 147968
// ---------------------------------------------------------------------------
constexpr int QST = 136;     // half stride
constexpr int PST = 72;      // half stride for P
constexpr int KVB = 64 * QST * 2;   // 17408 bytes per K/V stage

__device__ __forceinline__ void ld_kv_h(const __half* __restrict__ Kp,
                                        const __half* __restrict__ Vp,
                                        char* Ks, char* Vs, int k0, int tid) {
#pragma unroll
    for (int i = 0; i < 4; i++) {
        int fi = tid + BDIM * i;          // 1024 float4 per matrix
        int r  = fi >> 4;                 // 16 f4 per 128-half row
        int c8 = (fi & 15) * 8;
        cp_async16(Ks + (r * QST + c8) * 2, Kp + (size_t)(k0 + r) * DHc + c8);
        cp_async16(Vs + (r * QST + c8) * 2, Vp + (size_t)(k0 + r) * DHc + c8);
    }
}

__global__ void __launch_bounds__(BDIM) attn_kernel() {
    extern __shared__ __align__(16) char smc[];
    __half* Qs = (__half*)smc;
    char*   KB = smc + 17408;
    char*   VB = smc + 52224;
    float*  Ss = (float*)(smc + 87040);
    __half* Ps = (__half*)(smc + 104448);
    float*  Ac = (float*)(smc + 113664);
    float*  Ar = (float*)(smc + 147456);
    float*  Lr = (float*)(smc + 147712);

    const int tid  = threadIdx.x;
    const int warp = tid >> 5;
    const int q0 = (int)(gridDim.x - 1 - blockIdx.x) * 64;
    const int h  = blockIdx.y;
    const int bb = blockIdx.z;
    const size_t head_off = ((size_t)(bb * Hc + h) * Lc) * DHc;
    const __half* Qp = g_Qh + head_off;
    const __half* Kp = g_Kh + head_off;
    const __half* Vp = g_Vh + head_off;
    const float SC = SCALE_C;

    const int nkt = q0 / 64 + 1;
    const int tm = warp >> 1;            // PV: warp owns rows [tm*16, tm*16+16)

    ld_kv_h(Kp, Vp, KB, VB, 0, tid);
    cp_commit();

    // Row-index pattern (learn accumulator-fragment row mapping at runtime)
    if (tid < 256) Ss[(tid >> 4) * 68 + (tid & 15)] = (float)(tid >> 4);
    // Load Q tile (64 x 128 half): 1024 f4, 4 per thread
#pragma unroll
    for (int i = 0; i < 4; i++) {
        int fi = tid + BDIM * i;
        int r  = fi >> 4;
        int c8 = (fi & 15) * 8;
        *(uint4*)((char*)Qs + (r * QST + c8) * 2) =
            *(const uint4*)(Qp + (size_t)(q0 + r) * DHc + c8);
    }
    __syncthreads();
    wmma::fragment<wmma::accumulator, 16, 16, 16, float> rowf;
    wmma::load_matrix_sync(rowf, Ss, 68, wmma::mem_row_major);

    wmma::fragment<wmma::accumulator, 16, 16, 16, float> of[4];
#pragma unroll
    for (int j = 0; j < 4; j++) wmma::fill_fragment(of[j], 0.0f);

    float mreg = -1e30f, lreg = 0.0f;    // per-quad replicated

    for (int kt = 0; kt < nkt; kt++) {
        const int k0 = kt * 64;
        const __half* Ks = (const __half*)(KB + (kt & 1) * KVB);
        const __half* Vs = (const __half*)(VB + (kt & 1) * KVB);

        cp_wait<0>();
        __syncthreads();
        if (kt + 1 < nkt) {
            ld_kv_h(Kp, Vp, KB + ((kt + 1) & 1) * KVB, VB + ((kt + 1) & 1) * KVB,
                    (kt + 1) * 64, tid);
        }
        cp_commit();

        // S = Q K^T (64x64): 2 tiles of 16x16 per warp, K=128 in 8 steps
#pragma unroll
        for (int j = 0; j < 2; j++) {
            int t = warp * 2 + j;
            int stm = t >> 2, stn = t & 3;
            wmma::fragment<wmma::accumulator, 16, 16, 16, float> sf;
            wmma::fill_fragment(sf, 0.0f);
#pragma unroll
            for (int kk = 0; kk < 128; kk += 16) {
                wmma::fragment<wmma::matrix_a, 16, 16, 16, __half, wmma::row_major> af;
                wmma::fragment<wmma::matrix_b, 16, 16, 16, __half, wmma::col_major> bf;
                wmma::load_matrix_sync(af, Qs + (stm * 16) * QST + kk, QST);
                wmma::load_matrix_sync(bf, Ks + (stn * 16) * QST + kk, QST);
                wmma::mma_sync(sf, af, bf, sf);
            }
            wmma::store_matrix_sync(Ss + (stm * 16) * 68 + stn * 16, sf, 68, wmma::mem_row_major);
        }
        __syncthreads();

        // Online softmax: 4 threads per row; P stored as fp16
        {
            int row = tid >> 2;
            int sub = tid & 3;
            int q = q0 + row;
            int vis = q - k0;
            float* srow = Ss + row * 68;
            __half* prow = Ps + row * PST;
            float mx = -1e30f;
#pragma unroll
            for (int c = sub * 16; c < sub * 16 + 16; c++)
                if (c <= vis) mx = fmaxf(mx, srow[c]);
            mx = fmaxf(mx, __shfl_xor_sync(0xffffffffu, mx, 1));
            mx = fmaxf(mx, __shfl_xor_sync(0xffffffffu, mx, 2));
            float mn = fmaxf(mreg, mx * SC);
            float alpha = __expf(mreg - mn);
            float sum = 0.0f;
#pragma unroll
            for (int c = sub * 16; c < sub * 16 + 16; c++) {
                float p = (c <= vis) ? __expf(srow[c] * SC - mn) : 0.0f;
                __half ph = __float2half(p);
                prow[c] = ph;
                sum += __half2float(ph);
            }
            sum += __shfl_xor_sync(0xffffffffu, sum, 1);
            sum += __shfl_xor_sync(0xffffffffu, sum, 2);
            lreg = lreg * alpha + sum;
            mreg = mn;
            if (sub == 0) Ar[row] = alpha;
        }
        __syncthreads();

        // Rescale persistent accumulators, then of += P * V
        {
            float av[8];
#pragma unroll
            for (int e = 0; e < 8; e++)
                av[e] = Ar[tm * 16 + (int)rowf.x[e]];
#pragma unroll
            for (int j = 0; j < 4; j++)
#pragma unroll
                for (int e = 0; e < 8; e++)
                    of[j].x[e] *= av[e];
        }
#pragma unroll
        for (int j = 0; j < 4; j++) {
            int tn = (warp & 1) * 4 + j;
#pragma unroll
            for (int kk = 0; kk < 64; kk += 16) {
                wmma::fragment<wmma::matrix_a, 16, 16, 16, __half, wmma::row_major> af;
                wmma::fragment<wmma::matrix_b, 16, 16, 16, __half, wmma::row_major> bf;
                wmma::load_matrix_sync(af, Ps + (tm * 16) * PST + kk, PST);
                wmma::load_matrix_sync(bf, Vs + kk * QST + tn * 16, QST);
                wmma::mma_sync(of[j], af, bf, of[j]);
            }
        }
    }

    // Epilogue: accumulators + l -> smem, normalize, write fp16 for oproj
#pragma unroll
    for (int j = 0; j < 4; j++) {
        int tn = (warp & 1) * 4 + j;
        wmma::store_matrix_sync(Ac + (tm * 16) * 132 + tn * 16, of[j], 132, wmma::mem_row_major);
    }
    if ((tid & 3) == 0) Lr[tid >> 2] = lreg;
    __syncthreads();

    for (int idx = tid; idx < 64 * 128; idx += BDIM) {
        int r = idx >> 7, d = idx & 127;
        size_t m = (size_t)bb * Lc + q0 + r;
        g_Ah[m * Dc + h * DHc + d] = __float2half(Ac[r * 132 + d] / Lr[r]);
    }
}

// ---------------------------------------------------------------------------
// Output projection: out = A * Wo^T. grid = (16, 32)
// ---------------------------------------------------------------------------
__global__ void __launch_bounds__(BDIM, 2)
oproj_kernel(float* __restrict__ out) {
    extern __shared__ __align__(16) char smc[];
    gemm_core_h(g_Ah, g_Woh, smc);
    float* cs = (float*)smc;
    const int m0 = blockIdx.y * 128;
    const int n0 = blockIdx.x * 128;
    const int tid = threadIdx.x;
    for (int idx = tid; idx < 128 * 128; idx += BDIM) {
        int r = idx >> 7, c = idx & 127;
        out[(size_t)(m0 + r) * Dc + n0 + c] = cs[r * 132 + c];
    }
}

// ---------------------------------------------------------------------------
extern "C" void kernel_launch(void* const* d_in, const int* in_sizes, int n_in,
                              void* d_out, int out_size) {
    const float* x    = (const float*)d_in[0];
    // d_in[1] = mask (unused: causal mask applied analytically)
    const float* cosT = (const float*)d_in[2];
    const float* sinT = (const float*)d_in[3];
    const float* wq   = (const float*)d_in[4];
    const float* wk   = (const float*)d_in[5];
    const float* wv   = (const float*)d_in[6];
    const float* wo   = (const float*)d_in[7];
    float* out = (float*)d_out;

    const int smemG = 128 * 132 * (int)sizeof(float);   // 67584 (cs dominates pipeline bufs)
    const int smemA = 147968;

    cudaFuncSetAttribute(proj_kernel,  cudaFuncAttributeMaxDynamicSharedMemorySize, smemG);
    cudaFuncSetAttribute(oproj_kernel, cudaFuncAttributeMaxDynamicSharedMemorySize, smemG);
    cudaFuncSetAttribute(attn_kernel,  cudaFuncAttributeMaxDynamicSharedMemorySize, smemA);

    constexpr size_t NTOT = (size_t)Bc * Lc * Dc + 4 * (size_t)Dc * Dc;  // 25165824
    cvt_kernel<<<(unsigned)(NTOT / 8 / 256), 256>>>(x, wq, wk, wv, wo);
    proj_kernel<<<dim3(Dc / 128, (Bc * Lc) / 128, 3), BDIM, smemG>>>(cosT, sinT);
    attn_kernel<<<dim3(Lc / 64, Hc, Bc), BDIM, smemA>>>();
    oproj_kernel<<<dim3(Dc / 128, (Bc * Lc) / 128, 1), BDIM, smemG>>>(out);
}